// round 13
// baseline (speedup 1.0000x reference)
#include <cuda_runtime.h>
#include <cuda_bf16.h>

#define NF      2048
#define NROWS   8192
#define RCHUNKS 512                 // chunks of 16 rows; also k_partial grid

// Scratch (allocation-free): partial sums/sumsqs + final stats
__device__ float g_psum[RCHUNKS * NF];   // 4 MiB
__device__ float g_psq [RCHUNKS * NF];   // 4 MiB
__device__ float g_mean[NF];
__device__ float g_istd[NF];

__device__ __forceinline__ void acc8(float4& s, float4& q, const float4 v) {
    s.x += v.x;       s.y += v.y;       s.z += v.z;       s.w += v.w;
    q.x += v.x * v.x; q.y += v.y * v.y; q.z += v.z * v.z; q.w += v.w * v.w;
}

// ---------------------------------------------------------------------------
// Pass 1: 512 CTAs, each streams ONE CONTIGUOUS 128 KB slab (16 rows).
// Step s (0..31) covers half-row s: float4 index slab + s*256 + t.
// Column of step s = (s%2)*1024 + 4t  -> two accumulator sets, no scatter.
// Early PDL trigger so downstream kernels prelaunch into free SM slots.
// ---------------------------------------------------------------------------
__global__ void __launch_bounds__(256) k_partial(const float* __restrict__ x) {
    cudaTriggerProgrammaticLaunchCompletion();

    const int c = blockIdx.x;                 // chunk [0,512)
    const int t = threadIdx.x;                // [0,256)
    const float4* xp = reinterpret_cast<const float4*>(x) + (size_t)c * 8192 + t;

    float4 s0 = make_float4(0.f,0.f,0.f,0.f), q0 = s0;
    float4 s1 = s0, q1 = s0;

    #pragma unroll 1
    for (int b = 0; b < 8; ++b) {             // 8 batches x 4 steps = 32 steps
        float4 buf[4];
        #pragma unroll
        for (int r = 0; r < 4; ++r) buf[r] = xp[(b * 4 + r) * 256];
        acc8(s0, q0, buf[0]);                 // even step -> cols 4t..4t+3
        acc8(s1, q1, buf[1]);                 // odd step  -> cols 1024+4t..
        acc8(s0, q0, buf[2]);
        acc8(s1, q1, buf[3]);
    }

    *reinterpret_cast<float4*>(g_psum + c * NF + 4 * t)        = s0;
    *reinterpret_cast<float4*>(g_psq  + c * NF + 4 * t)        = q0;
    *reinterpret_cast<float4*>(g_psum + c * NF + 1024 + 4 * t) = s1;
    *reinterpret_cast<float4*>(g_psq  + c * NF + 1024 + 4 * t) = q1;
}

// ---------------------------------------------------------------------------
// Pass 2: unchanged (partial layout identical). 128 blocks x 256 threads;
// 16 cols/block, 16 threads/col x 32 partials, fixed-order shared combine.
// var = (sumsq - N*mean^2)/(N-1)  (ddof=1, matches sequential Welford).
// ---------------------------------------------------------------------------
__global__ void __launch_bounds__(256) k_finish() {
    cudaTriggerProgrammaticLaunchCompletion();
    cudaGridDependencySynchronize();

    __shared__ float ssum[256];
    __shared__ float ssq [256];
    const int t  = threadIdx.x;
    const int cl = t & 15;
    const int j  = t >> 4;
    const int c  = blockIdx.x * 16 + cl;

    float s = 0.f, q = 0.f;
    #pragma unroll 8
    for (int k = j * 32; k < j * 32 + 32; ++k) {
        s += g_psum[k * NF + c];
        q += g_psq [k * NF + c];
    }
    ssum[t] = s;
    ssq [t] = q;
    __syncthreads();

    if (j == 0) {
        double S = 0.0, Q = 0.0;
        #pragma unroll
        for (int jj = 0; jj < 16; ++jj) {
            S += (double)ssum[jj * 16 + cl];
            Q += (double)ssq [jj * 16 + cl];
        }
        const double mean = S / (double)NROWS;
        const double var  = (Q - S * mean) / (double)(NROWS - 1);
        g_mean[c] = (float)mean;
        g_istd[c] = (float)(1.0 / sqrt(var + 1e-6));
    }
}

// ---------------------------------------------------------------------------
// Pass 3: 2048 CTAs, each owns ONE CONTIGUOUS 32 KB slab (4 rows, 8 steps
// of half-row per thread). All 8 x loads in the pre-sync PDL preamble
// (overlap upstream; L2 hits from pass 1). Column of step s = (s%2)*1024+4t
// -> only two (mean,istd) quads per thread. Sequential __stcs write stream.
// ---------------------------------------------------------------------------
__global__ void __launch_bounds__(256) k_norm(const float* __restrict__ x,
                                              float* __restrict__ out) {
    const int c = blockIdx.x;                 // [0,2048)
    const int t = threadIdx.x;
    const float4* xp = reinterpret_cast<const float4*>(x)  + (size_t)c * 2048 + t;
    float4*       op = reinterpret_cast<float4*>(out)      + (size_t)c * 2048 + t;

    float4 buf[8];
    #pragma unroll
    for (int s = 0; s < 8; ++s) buf[s] = __ldcs(xp + s * 256);

    cudaGridDependencySynchronize();          // wait for g_mean/g_istd

    const float4 m0 = *reinterpret_cast<const float4*>(g_mean + 4 * t);
    const float4 r0 = *reinterpret_cast<const float4*>(g_istd + 4 * t);
    const float4 m1 = *reinterpret_cast<const float4*>(g_mean + 1024 + 4 * t);
    const float4 r1 = *reinterpret_cast<const float4*>(g_istd + 1024 + 4 * t);

    #pragma unroll
    for (int s = 0; s < 8; ++s) {
        const float4 m = (s & 1) ? m1 : m0;
        const float4 r = (s & 1) ? r1 : r0;
        float4 o;
        o.x = (buf[s].x - m.x) * r.x;
        o.y = (buf[s].y - m.y) * r.y;
        o.z = (buf[s].z - m.z) * r.z;
        o.w = (buf[s].w - m.w) * r.w;
        __stcs(op + s * 256, o);
    }
}

extern "C" void kernel_launch(void* const* d_in, const int* in_sizes, int n_in,
                              void* d_out, int out_size) {
    const float* x = (const float*)d_in[0];   // [8192, 2048] fp32
    float* out = (float*)d_out;               // [8192, 2048] fp32

    k_partial<<<RCHUNKS, 256>>>(x);

    cudaLaunchAttribute pdl;
    pdl.id = cudaLaunchAttributeProgrammaticStreamSerialization;
    pdl.val.programmaticStreamSerializationAllowed = 1;

    {
        cudaLaunchConfig_t cfg = {};
        cfg.gridDim  = dim3(NF / 16);
        cfg.blockDim = dim3(256);
        cfg.attrs    = &pdl;
        cfg.numAttrs = 1;
        cfg.stream   = 0;
        cudaLaunchKernelEx(&cfg, k_finish);
    }
    {
        cudaLaunchConfig_t cfg = {};
        cfg.gridDim  = dim3(2048);
        cfg.blockDim = dim3(256);
        cfg.attrs    = &pdl;
        cfg.numAttrs = 1;
        cfg.stream   = 0;
        cudaLaunchKernelEx(&cfg, k_norm, x, out);
    }
}